// round 14
// baseline (speedup 1.0000x reference)
#include <cuda_runtime.h>
#include <cuda_fp16.h>
#include <cstdint>

#define N_DRUG 25000
#define N_DIS  25000
#define NN     50000
#define NE     800000
#define D      128
#define DH     (D / 2)     // half2 per row

// Scratch: __device__ globals (no allocations allowed).
__device__ __align__(16) float   g_deg[NN];
__device__ __align__(16) __half2 g_h2[(size_t)NN * DH];  // src-norm-scaled fp16 features

static __device__ __forceinline__ int clamp_idx(int v) {
    return v < 0 ? 0 : (v >= NN ? NN - 1 : v);
}

// ---------------------------------------------------------------------------
// Zero output (poisoned 0xAA) + degree counters.
// ---------------------------------------------------------------------------
__global__ void zero_kernel(float4* __restrict__ out4) {
    const int stride = gridDim.x * blockDim.x;
    const int i0 = blockIdx.x * blockDim.x + threadIdx.x;
    const int total4 = NN * D / 4;
    const float4 z = make_float4(0.f, 0.f, 0.f, 0.f);
    for (int t = i0; t < total4; t += stride) out4[t] = z;
    for (int t = i0; t < NN; t += stride) g_deg[t] = 0.f;
}

// ---------------------------------------------------------------------------
// Degree histogram: grid-stride, 4 edges per thread via int4.
// ---------------------------------------------------------------------------
__global__ void degree_kernel(const int4* __restrict__ rows4) {
    const int stride = gridDim.x * blockDim.x;
    for (int i = blockIdx.x * blockDim.x + threadIdx.x; i < NE / 4; i += stride) {
        int4 r = rows4[i];
        atomicAdd(&g_deg[clamp_idx(r.x)], 1.0f);
        atomicAdd(&g_deg[clamp_idx(r.y)], 1.0f);
        atomicAdd(&g_deg[clamp_idx(r.z)], 1.0f);
        atomicAdd(&g_deg[clamp_idx(r.w)], 1.0f);
    }
}

// ---------------------------------------------------------------------------
// Tensor-core projection via mma.sync.m16n8k16 (fp16 in, fp32 accumulate):
//   g_h2[base+row][:] = half( (f[row] @ W) * norm[base+row] )
// Block: 128 rows x 128 cols, 8 warps (16-row strip per warp).
// Smem (fp16, stride 136 halves): sWt[128][136] (transposed W), sF[128][136].
// Global loads vectorized as float4.
// ---------------------------------------------------------------------------
#define PD 136                     // padded row stride in halves
#define PROJ_TB 256
#define PROJ_ROWS 128

__device__ __forceinline__ void mma16816(float c[4], const uint32_t a[4],
                                         uint32_t b0, uint32_t b1) {
    asm volatile(
        "mma.sync.aligned.m16n8k16.row.col.f32.f16.f16.f32 "
        "{%0,%1,%2,%3}, {%4,%5,%6,%7}, {%8,%9}, {%0,%1,%2,%3};\n"
        : "+f"(c[0]), "+f"(c[1]), "+f"(c[2]), "+f"(c[3])
        : "r"(a[0]), "r"(a[1]), "r"(a[2]), "r"(a[3]), "r"(b0), "r"(b1));
}

extern __shared__ __half s_h[];

__global__ __launch_bounds__(PROJ_TB, 2)
void project_mma_kernel(const float* __restrict__ drug_f, const float* __restrict__ dis_f,
                        const float* __restrict__ drug_w, const float* __restrict__ dis_w) {
    __half* sWt = s_h;                       // [128][PD]  sWt[n][k]
    __half* sF  = s_h + 128 * PD;            // [128][PD]  sF[r][k]

    const int type = blockIdx.y;
    const float* __restrict__ f = type ? dis_f : drug_f;
    const float* __restrict__ W = type ? dis_w : drug_w;
    const int n_rows   = type ? N_DIS : N_DRUG;
    const int base     = type ? N_DRUG : 0;
    const int row_base = blockIdx.x * PROJ_ROWS;

    const int tid  = threadIdx.x;
    const int wid  = tid >> 5;
    const int lane = tid & 31;
    const int gid  = lane >> 2;      // group id 0..7
    const int tg   = lane & 3;       // thread-in-group 0..3

    // W transposed into smem, float4 global loads.
    for (int idx = tid; idx < D * D / 4; idx += PROJ_TB) {
        int k = idx >> 5;            // 32 float4 per W row
        int n = (idx & 31) * 4;
        float4 v = ((const float4*)W)[idx];
        sWt[(n + 0) * PD + k] = __float2half(v.x);
        sWt[(n + 1) * PD + k] = __float2half(v.y);
        sWt[(n + 2) * PD + k] = __float2half(v.z);
        sWt[(n + 3) * PD + k] = __float2half(v.w);
    }
    // f tile, float4 global loads, packed half2 smem stores (row-clamped tail).
    for (int idx = tid; idx < PROJ_ROWS * D / 4; idx += PROJ_TB) {
        int r  = idx >> 5;           // 32 float4 per f row
        int k4 = (idx & 31) * 4;
        int row = row_base + r;
        if (row >= n_rows) row = n_rows - 1;
        float4 v = ((const float4*)f)[(size_t)row * 32 + (idx & 31)];
        __half2 h0 = __floats2half2_rn(v.x, v.y);
        __half2 h1 = __floats2half2_rn(v.z, v.w);
        *(uint2*)&sF[r * PD + k4] = make_uint2(*(uint32_t*)&h0, *(uint32_t*)&h1);
    }
    __syncthreads();

    const int rowA = wid * 16;       // warp's row strip within the block

    // Preload all A fragments: 8 k-tiles x 4 regs.
    uint32_t A[8][4];
    #pragma unroll
    for (int kt = 0; kt < 8; ++kt) {
        int bk = kt * 16 + tg * 2;
        A[kt][0] = *(const uint32_t*)&sF[(rowA + gid)     * PD + bk];
        A[kt][1] = *(const uint32_t*)&sF[(rowA + gid + 8) * PD + bk];
        A[kt][2] = *(const uint32_t*)&sF[(rowA + gid)     * PD + bk + 8];
        A[kt][3] = *(const uint32_t*)&sF[(rowA + gid + 8) * PD + bk + 8];
    }

    float acc[16][4];
    #pragma unroll
    for (int nt = 0; nt < 16; ++nt)
        #pragma unroll
        for (int j = 0; j < 4; ++j) acc[nt][j] = 0.f;

    #pragma unroll
    for (int nt = 0; nt < 16; ++nt) {
        const int n0 = nt * 8 + gid;
        #pragma unroll
        for (int kt = 0; kt < 8; ++kt) {
            uint32_t b0 = *(const uint32_t*)&sWt[n0 * PD + kt * 16 + tg * 2];
            uint32_t b1 = *(const uint32_t*)&sWt[n0 * PD + kt * 16 + tg * 2 + 8];
            mma16816(acc[nt], A[kt], b0, b1);
        }
    }

    // Store with fused source-side norm, fp16.
    const int r0 = row_base + rowA + gid;
    const int r1 = r0 + 8;
    if (r0 < n_rows) {
        int node = base + r0;
        float nrm = rsqrtf(fmaxf(g_deg[node], 1.0f));
        #pragma unroll
        for (int nt = 0; nt < 16; ++nt)
            g_h2[(size_t)node * DH + nt * 4 + tg] =
                __floats2half2_rn(acc[nt][0] * nrm, acc[nt][1] * nrm);
    }
    if (r1 < n_rows) {
        int node = base + r1;
        float nrm = rsqrtf(fmaxf(g_deg[node], 1.0f));
        #pragma unroll
        for (int nt = 0; nt < 16; ++nt)
            g_h2[(size_t)node * DH + nt * 4 + tg] =
                __floats2half2_rn(acc[nt][2] * nrm, acc[nt][3] * nrm);
    }
}

// ---------------------------------------------------------------------------
// Scatter: one warp per FOUR edges. Minimal memory-instruction mix:
//   per edge = 1 gather LDG.128 (fp16) + 1 RED.128. No deg load, no rsqrt,
//   no multiplies beyond the h2f converts (dest norm applied by scale_kernel).
// ---------------------------------------------------------------------------
__global__ __launch_bounds__(256)
void edge_scatter_kernel(const int4* __restrict__ rows4,
                         const int4* __restrict__ cols4,
                         float* __restrict__ out) {
    const int w    = (blockIdx.x * blockDim.x + threadIdx.x) >> 5;  // warp = 4 edges
    const int lane = threadIdx.x & 31;
    if (w >= NE / 4) return;

    int4 rr = __ldg(&rows4[w]);   // lane-uniform -> broadcast
    int4 cc = __ldg(&cols4[w]);

    int r0 = clamp_idx(rr.x), r1 = clamp_idx(rr.y);
    int r2 = clamp_idx(rr.z), r3 = clamp_idx(rr.w);
    int c0 = clamp_idx(cc.x), c1 = clamp_idx(cc.y);
    int c2 = clamp_idx(cc.z), c3 = clamp_idx(cc.w);

    const int hoff = lane * 2;            // half2 index within row
    uint2 p0 = *(const uint2*)&g_h2[(size_t)c0 * DH + hoff];
    uint2 p1 = *(const uint2*)&g_h2[(size_t)c1 * DH + hoff];
    uint2 p2 = *(const uint2*)&g_h2[(size_t)c2 * DH + hoff];
    uint2 p3 = *(const uint2*)&g_h2[(size_t)c3 * DH + hoff];

    const size_t lo = (size_t)lane * 4;
    float* d0 = &out[(size_t)r0 * D + lo];
    float* d1 = &out[(size_t)r1 * D + lo];
    float* d2 = &out[(size_t)r2 * D + lo];
    float* d3 = &out[(size_t)r3 * D + lo];

    float2 a, b;
    a = __half22float2(*(__half2*)&p0.x); b = __half22float2(*(__half2*)&p0.y);
    asm volatile("red.global.add.v4.f32 [%0], {%1,%2,%3,%4};"
                 :: "l"(d0), "f"(a.x), "f"(a.y), "f"(b.x), "f"(b.y) : "memory");
    a = __half22float2(*(__half2*)&p1.x); b = __half22float2(*(__half2*)&p1.y);
    asm volatile("red.global.add.v4.f32 [%0], {%1,%2,%3,%4};"
                 :: "l"(d1), "f"(a.x), "f"(a.y), "f"(b.x), "f"(b.y) : "memory");
    a = __half22float2(*(__half2*)&p2.x); b = __half22float2(*(__half2*)&p2.y);
    asm volatile("red.global.add.v4.f32 [%0], {%1,%2,%3,%4};"
                 :: "l"(d2), "f"(a.x), "f"(a.y), "f"(b.x), "f"(b.y) : "memory");
    a = __half22float2(*(__half2*)&p3.x); b = __half22float2(*(__half2*)&p3.y);
    asm volatile("red.global.add.v4.f32 [%0], {%1,%2,%3,%4};"
                 :: "l"(d3), "f"(a.x), "f"(a.y), "f"(b.x), "f"(b.y) : "memory");
}

// ---------------------------------------------------------------------------
// Final dest-side symmetric-norm scale: out[i][:] *= rsqrt(max(deg[i],1)).
// Matches the reference's post-multiply exactly.
// ---------------------------------------------------------------------------
__global__ __launch_bounds__(256)
void scale_kernel(float* __restrict__ out) {
    const int idx  = blockIdx.x * blockDim.x + threadIdx.x;  // one per float4
    const int row  = idx >> 5;
    const int lane = idx & 31;
    if (row >= NN) return;
    const float nrm = rsqrtf(fmaxf(g_deg[row], 1.0f));
    float4* p = (float4*)&out[(size_t)row * D + lane * 4];
    float4 v = *p;
    v.x *= nrm; v.y *= nrm; v.z *= nrm; v.w *= nrm;
    *p = v;
}

// ---------------------------------------------------------------------------
// Launch sequence (stream 0, graph-capturable, allocation-free).
// Input order per metadata: drug_f, disease_f, drug_w, disease_w, rows, cols.
// ---------------------------------------------------------------------------
extern "C" void kernel_launch(void* const* d_in, const int* in_sizes, int n_in,
                              void* d_out, int out_size) {
    const float* drug_f = (const float*)d_in[0];
    const float* dis_f  = (const float*)d_in[1];
    const float* drug_w = (const float*)d_in[2];
    const float* dis_w  = (const float*)d_in[3];
    const int*   rows   = (const int*)d_in[4];
    const int*   cols   = (const int*)d_in[5];
    float* out = (float*)d_out;

    // 1) zero output + degree counters
    zero_kernel<<<2048, 256>>>((float4*)out);

    // 2) degree histogram (4 edges/thread, grid-stride)
    degree_kernel<<<784, 256>>>((const int4*)rows);

    // 3) tensor-core projection (+ source-side norm), fp16 store
    const int smem_bytes = 2 * 128 * PD * sizeof(__half);   // 69632 B
    (void)cudaFuncSetAttribute(project_mma_kernel,
                               cudaFuncAttributeMaxDynamicSharedMemorySize,
                               smem_bytes);
    dim3 pgrid((N_DRUG + PROJ_ROWS - 1) / PROJ_ROWS, 2);
    project_mma_kernel<<<pgrid, PROJ_TB, smem_bytes>>>(drug_f, dis_f, drug_w, dis_w);

    // 4) edge scatter: minimal per-edge mem-instruction mix
    edge_scatter_kernel<<<NE / 4 / 8, 256>>>((const int4*)rows,
                                             (const int4*)cols, out);

    // 5) dest-side norm scale
    scale_kernel<<<(NN * 32) / 256, 256>>>(out);
}

// round 15
// speedup vs baseline: 1.0391x; 1.0391x over previous
#include <cuda_runtime.h>
#include <cuda_fp16.h>
#include <cstdint>

#define N_DRUG 25000
#define N_DIS  25000
#define NN     50000
#define NE     800000
#define D      128
#define DH     (D / 2)     // half2 per row

// Scratch: __device__ globals (no allocations allowed).
__device__ __align__(16) float   g_deg[NN];
__device__ __align__(16) float   g_nrm[NN];              // rsqrt(max(deg,1)), by proj
__device__ __align__(16) __half2 g_h2[(size_t)NN * DH];  // src-norm-scaled fp16 features

static __device__ __forceinline__ int clamp_idx(int v) {
    return v < 0 ? 0 : (v >= NN ? NN - 1 : v);
}

// ---------------------------------------------------------------------------
// Zero output (poisoned 0xAA) + degree counters.
// ---------------------------------------------------------------------------
__global__ void zero_kernel(float4* __restrict__ out4) {
    const int stride = gridDim.x * blockDim.x;
    const int i0 = blockIdx.x * blockDim.x + threadIdx.x;
    const int total4 = NN * D / 4;
    const float4 z = make_float4(0.f, 0.f, 0.f, 0.f);
    for (int t = i0; t < total4; t += stride) out4[t] = z;
    for (int t = i0; t < NN; t += stride) g_deg[t] = 0.f;
}

// ---------------------------------------------------------------------------
// Degree histogram: grid-stride, 4 edges per thread via int4.
// ---------------------------------------------------------------------------
__global__ void degree_kernel(const int4* __restrict__ rows4) {
    const int stride = gridDim.x * blockDim.x;
    for (int i = blockIdx.x * blockDim.x + threadIdx.x; i < NE / 4; i += stride) {
        int4 r = rows4[i];
        atomicAdd(&g_deg[clamp_idx(r.x)], 1.0f);
        atomicAdd(&g_deg[clamp_idx(r.y)], 1.0f);
        atomicAdd(&g_deg[clamp_idx(r.z)], 1.0f);
        atomicAdd(&g_deg[clamp_idx(r.w)], 1.0f);
    }
}

// ---------------------------------------------------------------------------
// Tensor-core projection via mma.sync.m16n8k16 (fp16 in, fp32 accumulate):
//   g_h2[base+row][:] = half( (f[row] @ W) * norm[base+row] )
// Also publishes g_nrm[node] (each node touched exactly once across the grid).
// Block: 128 rows x 128 cols, 8 warps (16-row strip per warp).
// Smem (fp16, stride 136 halves): sWt[128][136] (transposed W), sF[128][136].
// Global loads vectorized as float4.
// ---------------------------------------------------------------------------
#define PD 136                     // padded row stride in halves
#define PROJ_TB 256
#define PROJ_ROWS 128

__device__ __forceinline__ void mma16816(float c[4], const uint32_t a[4],
                                         uint32_t b0, uint32_t b1) {
    asm volatile(
        "mma.sync.aligned.m16n8k16.row.col.f32.f16.f16.f32 "
        "{%0,%1,%2,%3}, {%4,%5,%6,%7}, {%8,%9}, {%0,%1,%2,%3};\n"
        : "+f"(c[0]), "+f"(c[1]), "+f"(c[2]), "+f"(c[3])
        : "r"(a[0]), "r"(a[1]), "r"(a[2]), "r"(a[3]), "r"(b0), "r"(b1));
}

extern __shared__ __half s_h[];

__global__ __launch_bounds__(PROJ_TB, 2)
void project_mma_kernel(const float* __restrict__ drug_f, const float* __restrict__ dis_f,
                        const float* __restrict__ drug_w, const float* __restrict__ dis_w) {
    __half* sWt = s_h;                       // [128][PD]  sWt[n][k]
    __half* sF  = s_h + 128 * PD;            // [128][PD]  sF[r][k]

    const int type = blockIdx.y;
    const float* __restrict__ f = type ? dis_f : drug_f;
    const float* __restrict__ W = type ? dis_w : drug_w;
    const int n_rows   = type ? N_DIS : N_DRUG;
    const int base     = type ? N_DRUG : 0;
    const int row_base = blockIdx.x * PROJ_ROWS;

    const int tid  = threadIdx.x;
    const int wid  = tid >> 5;
    const int lane = tid & 31;
    const int gid  = lane >> 2;      // group id 0..7
    const int tg   = lane & 3;       // thread-in-group 0..3

    // W transposed into smem, float4 global loads.
    for (int idx = tid; idx < D * D / 4; idx += PROJ_TB) {
        int k = idx >> 5;            // 32 float4 per W row
        int n = (idx & 31) * 4;
        float4 v = ((const float4*)W)[idx];
        sWt[(n + 0) * PD + k] = __float2half(v.x);
        sWt[(n + 1) * PD + k] = __float2half(v.y);
        sWt[(n + 2) * PD + k] = __float2half(v.z);
        sWt[(n + 3) * PD + k] = __float2half(v.w);
    }
    // f tile, float4 global loads, packed half2 smem stores (row-clamped tail).
    for (int idx = tid; idx < PROJ_ROWS * D / 4; idx += PROJ_TB) {
        int r  = idx >> 5;           // 32 float4 per f row
        int k4 = (idx & 31) * 4;
        int row = row_base + r;
        if (row >= n_rows) row = n_rows - 1;
        float4 v = ((const float4*)f)[(size_t)row * 32 + (idx & 31)];
        __half2 h0 = __floats2half2_rn(v.x, v.y);
        __half2 h1 = __floats2half2_rn(v.z, v.w);
        *(uint2*)&sF[r * PD + k4] = make_uint2(*(uint32_t*)&h0, *(uint32_t*)&h1);
    }
    __syncthreads();

    const int rowA = wid * 16;       // warp's row strip within the block

    // Preload all A fragments: 8 k-tiles x 4 regs.
    uint32_t A[8][4];
    #pragma unroll
    for (int kt = 0; kt < 8; ++kt) {
        int bk = kt * 16 + tg * 2;
        A[kt][0] = *(const uint32_t*)&sF[(rowA + gid)     * PD + bk];
        A[kt][1] = *(const uint32_t*)&sF[(rowA + gid + 8) * PD + bk];
        A[kt][2] = *(const uint32_t*)&sF[(rowA + gid)     * PD + bk + 8];
        A[kt][3] = *(const uint32_t*)&sF[(rowA + gid + 8) * PD + bk + 8];
    }

    float acc[16][4];
    #pragma unroll
    for (int nt = 0; nt < 16; ++nt)
        #pragma unroll
        for (int j = 0; j < 4; ++j) acc[nt][j] = 0.f;

    #pragma unroll
    for (int nt = 0; nt < 16; ++nt) {
        const int n0 = nt * 8 + gid;
        #pragma unroll
        for (int kt = 0; kt < 8; ++kt) {
            uint32_t b0 = *(const uint32_t*)&sWt[n0 * PD + kt * 16 + tg * 2];
            uint32_t b1 = *(const uint32_t*)&sWt[n0 * PD + kt * 16 + tg * 2 + 8];
            mma16816(acc[nt], A[kt], b0, b1);
        }
    }

    // Store with fused source-side norm (fp16) and publish g_nrm.
    const int r0 = row_base + rowA + gid;
    const int r1 = r0 + 8;
    if (r0 < n_rows) {
        int node = base + r0;
        float nrm = rsqrtf(fmaxf(g_deg[node], 1.0f));
        if (tg == 0) g_nrm[node] = nrm;
        #pragma unroll
        for (int nt = 0; nt < 16; ++nt)
            g_h2[(size_t)node * DH + nt * 4 + tg] =
                __floats2half2_rn(acc[nt][0] * nrm, acc[nt][1] * nrm);
    }
    if (r1 < n_rows) {
        int node = base + r1;
        float nrm = rsqrtf(fmaxf(g_deg[node], 1.0f));
        if (tg == 0) g_nrm[node] = nrm;
        #pragma unroll
        for (int nt = 0; nt < 16; ++nt)
            g_h2[(size_t)node * DH + nt * 4 + tg] =
                __floats2half2_rn(acc[nt][2] * nrm, acc[nt][3] * nrm);
    }
}

// ---------------------------------------------------------------------------
// Scatter: one warp per FOUR edges (fused dest norm — R13 structure).
//   - rows/cols fetched as one broadcast int4 each
//   - 4 independent fp16 gathers (256B/edge), norms from precomputed g_nrm
//   - accumulate fp32 via red.global.add.v4.f32
// ---------------------------------------------------------------------------
__global__ __launch_bounds__(256)
void edge_scatter_kernel(const int4* __restrict__ rows4,
                         const int4* __restrict__ cols4,
                         float* __restrict__ out) {
    const int w    = (blockIdx.x * blockDim.x + threadIdx.x) >> 5;  // warp = 4 edges
    const int lane = threadIdx.x & 31;
    if (w >= NE / 4) return;

    int4 rr = __ldg(&rows4[w]);   // lane-uniform -> broadcast
    int4 cc = __ldg(&cols4[w]);

    int r0 = clamp_idx(rr.x), r1 = clamp_idx(rr.y);
    int r2 = clamp_idx(rr.z), r3 = clamp_idx(rr.w);
    int c0 = clamp_idx(cc.x), c1 = clamp_idx(cc.y);
    int c2 = clamp_idx(cc.z), c3 = clamp_idx(cc.w);

    const int hoff = lane * 2;            // half2 index within row
    uint2 p0 = *(const uint2*)&g_h2[(size_t)c0 * DH + hoff];
    uint2 p1 = *(const uint2*)&g_h2[(size_t)c1 * DH + hoff];
    uint2 p2 = *(const uint2*)&g_h2[(size_t)c2 * DH + hoff];
    uint2 p3 = *(const uint2*)&g_h2[(size_t)c3 * DH + hoff];

    float n0 = __ldg(&g_nrm[r0]);
    float n1 = __ldg(&g_nrm[r1]);
    float n2 = __ldg(&g_nrm[r2]);
    float n3 = __ldg(&g_nrm[r3]);

    const size_t lo = (size_t)lane * 4;
    float* d0 = &out[(size_t)r0 * D + lo];
    float* d1 = &out[(size_t)r1 * D + lo];
    float* d2 = &out[(size_t)r2 * D + lo];
    float* d3 = &out[(size_t)r3 * D + lo];

    float2 a, b;
    a = __half22float2(*(__half2*)&p0.x); b = __half22float2(*(__half2*)&p0.y);
    asm volatile("red.global.add.v4.f32 [%0], {%1,%2,%3,%4};"
                 :: "l"(d0), "f"(a.x * n0), "f"(a.y * n0), "f"(b.x * n0), "f"(b.y * n0)
                 : "memory");
    a = __half22float2(*(__half2*)&p1.x); b = __half22float2(*(__half2*)&p1.y);
    asm volatile("red.global.add.v4.f32 [%0], {%1,%2,%3,%4};"
                 :: "l"(d1), "f"(a.x * n1), "f"(a.y * n1), "f"(b.x * n1), "f"(b.y * n1)
                 : "memory");
    a = __half22float2(*(__half2*)&p2.x); b = __half22float2(*(__half2*)&p2.y);
    asm volatile("red.global.add.v4.f32 [%0], {%1,%2,%3,%4};"
                 :: "l"(d2), "f"(a.x * n2), "f"(a.y * n2), "f"(b.x * n2), "f"(b.y * n2)
                 : "memory");
    a = __half22float2(*(__half2*)&p3.x); b = __half22float2(*(__half2*)&p3.y);
    asm volatile("red.global.add.v4.f32 [%0], {%1,%2,%3,%4};"
                 :: "l"(d3), "f"(a.x * n3), "f"(a.y * n3), "f"(b.x * n3), "f"(b.y * n3)
                 : "memory");
}

// ---------------------------------------------------------------------------
// Launch sequence (stream 0, graph-capturable, allocation-free).
// Input order per metadata: drug_f, disease_f, drug_w, disease_w, rows, cols.
// ---------------------------------------------------------------------------
extern "C" void kernel_launch(void* const* d_in, const int* in_sizes, int n_in,
                              void* d_out, int out_size) {
    const float* drug_f = (const float*)d_in[0];
    const float* dis_f  = (const float*)d_in[1];
    const float* drug_w = (const float*)d_in[2];
    const float* dis_w  = (const float*)d_in[3];
    const int*   rows   = (const int*)d_in[4];
    const int*   cols   = (const int*)d_in[5];
    float* out = (float*)d_out;

    // 1) zero output + degree counters
    zero_kernel<<<2048, 256>>>((float4*)out);

    // 2) degree histogram (4 edges/thread, grid-stride)
    degree_kernel<<<784, 256>>>((const int4*)rows);

    // 3) tensor-core projection (+ source-side norm, publishes g_nrm)
    const int smem_bytes = 2 * 128 * PD * sizeof(__half);   // 69632 B
    (void)cudaFuncSetAttribute(project_mma_kernel,
                               cudaFuncAttributeMaxDynamicSharedMemorySize,
                               smem_bytes);
    dim3 pgrid((N_DRUG + PROJ_ROWS - 1) / PROJ_ROWS, 2);
    project_mma_kernel<<<pgrid, PROJ_TB, smem_bytes>>>(drug_f, dis_f, drug_w, dis_w);

    // 4) edge scatter: 4 edges/warp, fp16 gathers, fused dest norm, RED.v4
    edge_scatter_kernel<<<NE / 4 / 8, 256>>>((const int4*)rows,
                                             (const int4*)cols, out);
}

// round 16
// speedup vs baseline: 1.0893x; 1.0483x over previous
#include <cuda_runtime.h>
#include <cuda_fp16.h>
#include <cstdint>

#define N_DRUG 25000
#define N_DIS  25000
#define NN     50000
#define NE     800000
#define D      128
#define DH     (D / 2)     // half2 per row

// Scratch: __device__ globals (no allocations allowed).
__device__ __align__(16) float   g_deg[NN];
__device__ __align__(16) __half2 g_h2[(size_t)NN * DH];  // src-norm-scaled fp16 features

static __device__ __forceinline__ int clamp_idx(int v) {
    return v < 0 ? 0 : (v >= NN ? NN - 1 : v);
}

// ---------------------------------------------------------------------------
// Zero output (poisoned 0xAA) + degree counters.
// ---------------------------------------------------------------------------
__global__ void zero_kernel(float4* __restrict__ out4) {
    const int stride = gridDim.x * blockDim.x;
    const int i0 = blockIdx.x * blockDim.x + threadIdx.x;
    const int total4 = NN * D / 4;
    const float4 z = make_float4(0.f, 0.f, 0.f, 0.f);
    for (int t = i0; t < total4; t += stride) out4[t] = z;
    for (int t = i0; t < NN; t += stride) g_deg[t] = 0.f;
}

// ---------------------------------------------------------------------------
// Degree histogram: grid-stride, 4 edges per thread via int4.
// ---------------------------------------------------------------------------
__global__ void degree_kernel(const int4* __restrict__ rows4) {
    const int stride = gridDim.x * blockDim.x;
    for (int i = blockIdx.x * blockDim.x + threadIdx.x; i < NE / 4; i += stride) {
        int4 r = rows4[i];
        atomicAdd(&g_deg[clamp_idx(r.x)], 1.0f);
        atomicAdd(&g_deg[clamp_idx(r.y)], 1.0f);
        atomicAdd(&g_deg[clamp_idx(r.z)], 1.0f);
        atomicAdd(&g_deg[clamp_idx(r.w)], 1.0f);
    }
}

// ---------------------------------------------------------------------------
// Tensor-core projection via mma.sync.m16n8k16 (fp16 in, fp32 accumulate):
//   g_h2[base+row][:] = half( (f[row] @ W) * norm[base+row] )
// Block: 128 rows x 128 cols, 8 warps (16-row strip per warp).  (R13 config)
// ---------------------------------------------------------------------------
#define PD 136                     // padded row stride in halves
#define PROJ_TB 256
#define PROJ_ROWS 128

__device__ __forceinline__ void mma16816(float c[4], const uint32_t a[4],
                                         uint32_t b0, uint32_t b1) {
    asm volatile(
        "mma.sync.aligned.m16n8k16.row.col.f32.f16.f16.f32 "
        "{%0,%1,%2,%3}, {%4,%5,%6,%7}, {%8,%9}, {%0,%1,%2,%3};\n"
        : "+f"(c[0]), "+f"(c[1]), "+f"(c[2]), "+f"(c[3])
        : "r"(a[0]), "r"(a[1]), "r"(a[2]), "r"(a[3]), "r"(b0), "r"(b1));
}

extern __shared__ __half s_h[];

__global__ __launch_bounds__(PROJ_TB, 2)
void project_mma_kernel(const float* __restrict__ drug_f, const float* __restrict__ dis_f,
                        const float* __restrict__ drug_w, const float* __restrict__ dis_w) {
    __half* sWt = s_h;                       // [128][PD]  sWt[n][k]
    __half* sF  = s_h + 128 * PD;            // [128][PD]  sF[r][k]

    const int type = blockIdx.y;
    const float* __restrict__ f = type ? dis_f : drug_f;
    const float* __restrict__ W = type ? dis_w : drug_w;
    const int n_rows   = type ? N_DIS : N_DRUG;
    const int base     = type ? N_DRUG : 0;
    const int row_base = blockIdx.x * PROJ_ROWS;

    const int tid  = threadIdx.x;
    const int wid  = tid >> 5;
    const int lane = tid & 31;
    const int gid  = lane >> 2;      // group id 0..7
    const int tg   = lane & 3;       // thread-in-group 0..3

    // Load W transposed into smem (coalesced global read).
    for (int idx = tid; idx < D * D; idx += PROJ_TB) {
        int k = idx >> 7, n = idx & 127;
        sWt[n * PD + k] = __float2half(W[idx]);
    }
    // Load the f tile (row-clamped for tail block).
    for (int idx = tid; idx < PROJ_ROWS * D; idx += PROJ_TB) {
        int r = idx >> 7, k = idx & 127;
        int row = row_base + r;
        if (row >= n_rows) row = n_rows - 1;
        sF[r * PD + k] = __float2half(f[(size_t)row * D + k]);
    }
    __syncthreads();

    const int rowA = wid * 16;       // warp's row strip within the block

    uint32_t A[8][4];
    #pragma unroll
    for (int kt = 0; kt < 8; ++kt) {
        int bk = kt * 16 + tg * 2;
        A[kt][0] = *(const uint32_t*)&sF[(rowA + gid)     * PD + bk];
        A[kt][1] = *(const uint32_t*)&sF[(rowA + gid + 8) * PD + bk];
        A[kt][2] = *(const uint32_t*)&sF[(rowA + gid)     * PD + bk + 8];
        A[kt][3] = *(const uint32_t*)&sF[(rowA + gid + 8) * PD + bk + 8];
    }

    float acc[16][4];
    #pragma unroll
    for (int nt = 0; nt < 16; ++nt)
        #pragma unroll
        for (int j = 0; j < 4; ++j) acc[nt][j] = 0.f;

    #pragma unroll
    for (int nt = 0; nt < 16; ++nt) {
        const int n0 = nt * 8 + gid;
        #pragma unroll
        for (int kt = 0; kt < 8; ++kt) {
            uint32_t b0 = *(const uint32_t*)&sWt[n0 * PD + kt * 16 + tg * 2];
            uint32_t b1 = *(const uint32_t*)&sWt[n0 * PD + kt * 16 + tg * 2 + 8];
            mma16816(acc[nt], A[kt], b0, b1);
        }
    }

    // Store with fused source-side norm, fp16.
    const int r0 = row_base + rowA + gid;
    const int r1 = r0 + 8;
    if (r0 < n_rows) {
        int node = base + r0;
        float nrm = rsqrtf(fmaxf(g_deg[node], 1.0f));
        #pragma unroll
        for (int nt = 0; nt < 16; ++nt)
            g_h2[(size_t)node * DH + nt * 4 + tg] =
                __floats2half2_rn(acc[nt][0] * nrm, acc[nt][1] * nrm);
    }
    if (r1 < n_rows) {
        int node = base + r1;
        float nrm = rsqrtf(fmaxf(g_deg[node], 1.0f));
        #pragma unroll
        for (int nt = 0; nt < 16; ++nt)
            g_h2[(size_t)node * DH + nt * 4 + tg] =
                __floats2half2_rn(acc[nt][2] * nrm, acc[nt][3] * nrm);
    }
}

// ---------------------------------------------------------------------------
// Scatter: one warp per EIGHT edges.
//   - 2 broadcast int4 loads each for rows/cols (0.25 idx loads/edge)
//   - 8 independent fp16 gathers (256B each) in flight (MLP=8)
//   - destination norm fused (deg load + rsqrt, proven free under mem floor)
//   - accumulate fp32 via red.global.add.v4.f32
// ---------------------------------------------------------------------------
__global__ __launch_bounds__(256)
void edge_scatter_kernel(const int4* __restrict__ rows4,
                         const int4* __restrict__ cols4,
                         float* __restrict__ out) {
    const int w    = (blockIdx.x * blockDim.x + threadIdx.x) >> 5;  // warp = 8 edges
    const int lane = threadIdx.x & 31;
    if (w >= NE / 8) return;

    int4 rrA = __ldg(&rows4[2 * w]);
    int4 rrB = __ldg(&rows4[2 * w + 1]);
    int4 ccA = __ldg(&cols4[2 * w]);
    int4 ccB = __ldg(&cols4[2 * w + 1]);

    int r[8], c[8];
    r[0] = clamp_idx(rrA.x); r[1] = clamp_idx(rrA.y);
    r[2] = clamp_idx(rrA.z); r[3] = clamp_idx(rrA.w);
    r[4] = clamp_idx(rrB.x); r[5] = clamp_idx(rrB.y);
    r[6] = clamp_idx(rrB.z); r[7] = clamp_idx(rrB.w);
    c[0] = clamp_idx(ccA.x); c[1] = clamp_idx(ccA.y);
    c[2] = clamp_idx(ccA.z); c[3] = clamp_idx(ccA.w);
    c[4] = clamp_idx(ccB.x); c[5] = clamp_idx(ccB.y);
    c[6] = clamp_idx(ccB.z); c[7] = clamp_idx(ccB.w);

    const int hoff = lane * 2;            // half2 index within row

    uint2 p[8];
    #pragma unroll
    for (int i = 0; i < 8; ++i)
        p[i] = *(const uint2*)&g_h2[(size_t)c[i] * DH + hoff];

    float n[8];
    #pragma unroll
    for (int i = 0; i < 8; ++i)
        n[i] = rsqrtf(fmaxf(__ldg(&g_deg[r[i]]), 1.0f));

    const size_t lo = (size_t)lane * 4;
    #pragma unroll
    for (int i = 0; i < 8; ++i) {
        float2 a = __half22float2(*(__half2*)&p[i].x);
        float2 b = __half22float2(*(__half2*)&p[i].y);
        float* d = &out[(size_t)r[i] * D + lo];
        asm volatile("red.global.add.v4.f32 [%0], {%1,%2,%3,%4};"
                     :: "l"(d), "f"(a.x * n[i]), "f"(a.y * n[i]),
                        "f"(b.x * n[i]), "f"(b.y * n[i])
                     : "memory");
    }
}

// ---------------------------------------------------------------------------
// Launch sequence (stream 0, graph-capturable, allocation-free).
// Input order per metadata: drug_f, disease_f, drug_w, disease_w, rows, cols.
// ---------------------------------------------------------------------------
extern "C" void kernel_launch(void* const* d_in, const int* in_sizes, int n_in,
                              void* d_out, int out_size) {
    const float* drug_f = (const float*)d_in[0];
    const float* dis_f  = (const float*)d_in[1];
    const float* drug_w = (const float*)d_in[2];
    const float* dis_w  = (const float*)d_in[3];
    const int*   rows   = (const int*)d_in[4];
    const int*   cols   = (const int*)d_in[5];
    float* out = (float*)d_out;

    // 1) zero output + degree counters
    zero_kernel<<<2048, 256>>>((float4*)out);

    // 2) degree histogram (4 edges/thread, grid-stride)
    degree_kernel<<<784, 256>>>((const int4*)rows);

    // 3) tensor-core projection (+ source-side norm), fp16 store
    const int smem_bytes = 2 * 128 * PD * sizeof(__half);   // 69632 B
    (void)cudaFuncSetAttribute(project_mma_kernel,
                               cudaFuncAttributeMaxDynamicSharedMemorySize,
                               smem_bytes);
    dim3 pgrid((N_DRUG + PROJ_ROWS - 1) / PROJ_ROWS, 2);
    project_mma_kernel<<<pgrid, PROJ_TB, smem_bytes>>>(drug_f, dis_f, drug_w, dis_w);

    // 4) edge scatter: 8 edges/warp, fp16 gathers, fused dest norm, RED.v4
    edge_scatter_kernel<<<(NE / 8) * 32 / 256, 256>>>((const int4*)rows,
                                                      (const int4*)cols, out);
}

// round 17
// speedup vs baseline: 1.1081x; 1.0173x over previous
#include <cuda_runtime.h>
#include <cuda_fp16.h>
#include <cstdint>

#define N_DRUG 25000
#define N_DIS  25000
#define NN     50000
#define NE     800000
#define D      128
#define DH     (D / 2)     // half2 per row

// Scratch: __device__ globals (no allocations allowed).
__device__ __align__(16) float   g_deg[NN];
__device__ __align__(16) __half2 g_h2[(size_t)NN * DH];  // src-norm-scaled fp16 features

static __device__ __forceinline__ int clamp_idx(int v) {
    return v < 0 ? 0 : (v >= NN ? NN - 1 : v);
}

// ---------------------------------------------------------------------------
// Zero the degree counters only (fast, precedes the fused deg+zero kernel).
// ---------------------------------------------------------------------------
__global__ void zero_deg_kernel() {
    int i = blockIdx.x * blockDim.x + threadIdx.x;
    if (i < NN) g_deg[i] = 0.f;
}

// ---------------------------------------------------------------------------
// Fused: degree histogram (4 edges/thread via int4) + zero of out (poisoned
// 0xAA). The two are independent; fusing overlaps the 25.6 MB zero-fill with
// the histogram atomics instead of serializing them.
// ---------------------------------------------------------------------------
__global__ void deg_zero_kernel(const int4* __restrict__ rows4,
                                float4* __restrict__ out4) {
    const int stride = gridDim.x * blockDim.x;
    const int i0 = blockIdx.x * blockDim.x + threadIdx.x;
    const float4 z = make_float4(0.f, 0.f, 0.f, 0.f);
    const int total4 = NN * D / 4;
    for (int t = i0; t < total4; t += stride) out4[t] = z;
    for (int i = i0; i < NE / 4; i += stride) {
        int4 r = rows4[i];
        atomicAdd(&g_deg[clamp_idx(r.x)], 1.0f);
        atomicAdd(&g_deg[clamp_idx(r.y)], 1.0f);
        atomicAdd(&g_deg[clamp_idx(r.z)], 1.0f);
        atomicAdd(&g_deg[clamp_idx(r.w)], 1.0f);
    }
}

// ---------------------------------------------------------------------------
// Tensor-core projection via mma.sync.m16n8k16 (fp16 in, fp32 accumulate):
//   g_h2[base+row][:] = half( (f[row] @ W) * norm[base+row] )
// Block: 128 rows x 128 cols, 8 warps (16-row strip per warp).  (R13 config)
// ---------------------------------------------------------------------------
#define PD 136                     // padded row stride in halves
#define PROJ_TB 256
#define PROJ_ROWS 128

__device__ __forceinline__ void mma16816(float c[4], const uint32_t a[4],
                                         uint32_t b0, uint32_t b1) {
    asm volatile(
        "mma.sync.aligned.m16n8k16.row.col.f32.f16.f16.f32 "
        "{%0,%1,%2,%3}, {%4,%5,%6,%7}, {%8,%9}, {%0,%1,%2,%3};\n"
        : "+f"(c[0]), "+f"(c[1]), "+f"(c[2]), "+f"(c[3])
        : "r"(a[0]), "r"(a[1]), "r"(a[2]), "r"(a[3]), "r"(b0), "r"(b1));
}

extern __shared__ __half s_h[];

__global__ __launch_bounds__(PROJ_TB, 2)
void project_mma_kernel(const float* __restrict__ drug_f, const float* __restrict__ dis_f,
                        const float* __restrict__ drug_w, const float* __restrict__ dis_w) {
    __half* sWt = s_h;                       // [128][PD]  sWt[n][k]
    __half* sF  = s_h + 128 * PD;            // [128][PD]  sF[r][k]

    const int type = blockIdx.y;
    const float* __restrict__ f = type ? dis_f : drug_f;
    const float* __restrict__ W = type ? dis_w : drug_w;
    const int n_rows   = type ? N_DIS : N_DRUG;
    const int base     = type ? N_DRUG : 0;
    const int row_base = blockIdx.x * PROJ_ROWS;

    const int tid  = threadIdx.x;
    const int wid  = tid >> 5;
    const int lane = tid & 31;
    const int gid  = lane >> 2;      // group id 0..7
    const int tg   = lane & 3;       // thread-in-group 0..3

    // Load W transposed into smem (coalesced global read).
    for (int idx = tid; idx < D * D; idx += PROJ_TB) {
        int k = idx >> 7, n = idx & 127;
        sWt[n * PD + k] = __float2half(W[idx]);
    }
    // Load the f tile (row-clamped for tail block).
    for (int idx = tid; idx < PROJ_ROWS * D; idx += PROJ_TB) {
        int r = idx >> 7, k = idx & 127;
        int row = row_base + r;
        if (row >= n_rows) row = n_rows - 1;
        sF[r * PD + k] = __float2half(f[(size_t)row * D + k]);
    }
    __syncthreads();

    const int rowA = wid * 16;       // warp's row strip within the block

    uint32_t A[8][4];
    #pragma unroll
    for (int kt = 0; kt < 8; ++kt) {
        int bk = kt * 16 + tg * 2;
        A[kt][0] = *(const uint32_t*)&sF[(rowA + gid)     * PD + bk];
        A[kt][1] = *(const uint32_t*)&sF[(rowA + gid + 8) * PD + bk];
        A[kt][2] = *(const uint32_t*)&sF[(rowA + gid)     * PD + bk + 8];
        A[kt][3] = *(const uint32_t*)&sF[(rowA + gid + 8) * PD + bk + 8];
    }

    float acc[16][4];
    #pragma unroll
    for (int nt = 0; nt < 16; ++nt)
        #pragma unroll
        for (int j = 0; j < 4; ++j) acc[nt][j] = 0.f;

    #pragma unroll
    for (int nt = 0; nt < 16; ++nt) {
        const int n0 = nt * 8 + gid;
        #pragma unroll
        for (int kt = 0; kt < 8; ++kt) {
            uint32_t b0 = *(const uint32_t*)&sWt[n0 * PD + kt * 16 + tg * 2];
            uint32_t b1 = *(const uint32_t*)&sWt[n0 * PD + kt * 16 + tg * 2 + 8];
            mma16816(acc[nt], A[kt], b0, b1);
        }
    }

    // Store with fused source-side norm, fp16.
    const int r0 = row_base + rowA + gid;
    const int r1 = r0 + 8;
    if (r0 < n_rows) {
        int node = base + r0;
        float nrm = rsqrtf(fmaxf(g_deg[node], 1.0f));
        #pragma unroll
        for (int nt = 0; nt < 16; ++nt)
            g_h2[(size_t)node * DH + nt * 4 + tg] =
                __floats2half2_rn(acc[nt][0] * nrm, acc[nt][1] * nrm);
    }
    if (r1 < n_rows) {
        int node = base + r1;
        float nrm = rsqrtf(fmaxf(g_deg[node], 1.0f));
        #pragma unroll
        for (int nt = 0; nt < 16; ++nt)
            g_h2[(size_t)node * DH + nt * 4 + tg] =
                __floats2half2_rn(acc[nt][2] * nrm, acc[nt][3] * nrm);
    }
}

// ---------------------------------------------------------------------------
// Scatter: one warp per FOUR edges (best-measured R13 config).
//   - rows/cols fetched as one broadcast int4 each
//   - 4 independent fp16 gathers (256B each) in flight
//   - destination norm fused (deg load + rsqrt ride free under the mem floor)
//   - accumulate fp32 via red.global.add.v4.f32
// ---------------------------------------------------------------------------
__global__ __launch_bounds__(256)
void edge_scatter_kernel(const int4* __restrict__ rows4,
                         const int4* __restrict__ cols4,
                         float* __restrict__ out) {
    const int w    = (blockIdx.x * blockDim.x + threadIdx.x) >> 5;  // warp = 4 edges
    const int lane = threadIdx.x & 31;
    if (w >= NE / 4) return;

    int4 rr = __ldg(&rows4[w]);   // lane-uniform -> broadcast
    int4 cc = __ldg(&cols4[w]);

    int r0 = clamp_idx(rr.x), r1 = clamp_idx(rr.y);
    int r2 = clamp_idx(rr.z), r3 = clamp_idx(rr.w);
    int c0 = clamp_idx(cc.x), c1 = clamp_idx(cc.y);
    int c2 = clamp_idx(cc.z), c3 = clamp_idx(cc.w);

    const int hoff = lane * 2;            // half2 index within row
    uint2 p0 = *(const uint2*)&g_h2[(size_t)c0 * DH + hoff];
    uint2 p1 = *(const uint2*)&g_h2[(size_t)c1 * DH + hoff];
    uint2 p2 = *(const uint2*)&g_h2[(size_t)c2 * DH + hoff];
    uint2 p3 = *(const uint2*)&g_h2[(size_t)c3 * DH + hoff];

    float n0 = rsqrtf(fmaxf(__ldg(&g_deg[r0]), 1.0f));
    float n1 = rsqrtf(fmaxf(__ldg(&g_deg[r1]), 1.0f));
    float n2 = rsqrtf(fmaxf(__ldg(&g_deg[r2]), 1.0f));
    float n3 = rsqrtf(fmaxf(__ldg(&g_deg[r3]), 1.0f));

    const size_t lo = (size_t)lane * 4;
    float* d0 = &out[(size_t)r0 * D + lo];
    float* d1 = &out[(size_t)r1 * D + lo];
    float* d2 = &out[(size_t)r2 * D + lo];
    float* d3 = &out[(size_t)r3 * D + lo];

    float2 a, b;
    a = __half22float2(*(__half2*)&p0.x); b = __half22float2(*(__half2*)&p0.y);
    asm volatile("red.global.add.v4.f32 [%0], {%1,%2,%3,%4};"
                 :: "l"(d0), "f"(a.x * n0), "f"(a.y * n0), "f"(b.x * n0), "f"(b.y * n0)
                 : "memory");
    a = __half22float2(*(__half2*)&p1.x); b = __half22float2(*(__half2*)&p1.y);
    asm volatile("red.global.add.v4.f32 [%0], {%1,%2,%3,%4};"
                 :: "l"(d1), "f"(a.x * n1), "f"(a.y * n1), "f"(b.x * n1), "f"(b.y * n1)
                 : "memory");
    a = __half22float2(*(__half2*)&p2.x); b = __half22float2(*(__half2*)&p2.y);
    asm volatile("red.global.add.v4.f32 [%0], {%1,%2,%3,%4};"
                 :: "l"(d2), "f"(a.x * n2), "f"(a.y * n2), "f"(b.x * n2), "f"(b.y * n2)
                 : "memory");
    a = __half22float2(*(__half2*)&p3.x); b = __half22float2(*(__half2*)&p3.y);
    asm volatile("red.global.add.v4.f32 [%0], {%1,%2,%3,%4};"
                 :: "l"(d3), "f"(a.x * n3), "f"(a.y * n3), "f"(b.x * n3), "f"(b.y * n3)
                 : "memory");
}

// ---------------------------------------------------------------------------
// Launch sequence (stream 0, graph-capturable, allocation-free).
// Input order per metadata: drug_f, disease_f, drug_w, disease_w, rows, cols.
// ---------------------------------------------------------------------------
extern "C" void kernel_launch(void* const* d_in, const int* in_sizes, int n_in,
                              void* d_out, int out_size) {
    const float* drug_f = (const float*)d_in[0];
    const float* dis_f  = (const float*)d_in[1];
    const float* drug_w = (const float*)d_in[2];
    const float* dis_w  = (const float*)d_in[3];
    const int*   rows   = (const int*)d_in[4];
    const int*   cols   = (const int*)d_in[5];
    float* out = (float*)d_out;

    // 1) zero degree counters (tiny)
    zero_deg_kernel<<<(NN + 255) / 256, 256>>>();

    // 2) fused: degree histogram + zero of out
    deg_zero_kernel<<<1184, 256>>>((const int4*)rows, (float4*)out);

    // 3) tensor-core projection (+ source-side norm), fp16 store
    const int smem_bytes = 2 * 128 * PD * sizeof(__half);   // 69632 B
    (void)cudaFuncSetAttribute(project_mma_kernel,
                               cudaFuncAttributeMaxDynamicSharedMemorySize,
                               smem_bytes);
    dim3 pgrid((N_DRUG + PROJ_ROWS - 1) / PROJ_ROWS, 2);
    project_mma_kernel<<<pgrid, PROJ_TB, smem_bytes>>>(drug_f, dis_f, drug_w, dis_w);

    // 4) edge scatter: 4 edges/warp, fp16 gathers, fused dest norm, RED.v4
    edge_scatter_kernel<<<NE / 4 / 8, 256>>>((const int4*)rows,
                                             (const int4*)cols, out);
}